// round 15
// baseline (speedup 1.0000x reference)
#include <cuda_runtime.h>
#include <cuda_fp16.h>
#include <math.h>
#include <stdint.h>

#define B_ 4
#define T_ 2048
#define D_ 1024
#define M_ (B_*T_)

#define NT 128                  // 4 warps per CTA
#define BM 128
#define BN 128
#define BK 32                   // halves per k-chunk (64 B)
#define LDB_S 80                // bytes per smem row
#define TILE_B (128*LDB_S)      // 10240 B per operand tile
#define STAGE_B (2*TILE_B)      // 20480 B
#define NSTAGE 4
#define SMEM_B (NSTAGE*STAGE_B) // 81920 B
#define GRID_P 304              // persistent CTAs (2 per SM, 152 SMs)

// ---------------- scratch ------------------------------------------------------
__device__ __half g_h  [M_*D_];
__device__ __half g_qk [(size_t)M_*2048];
__device__ __half g_vt [(size_t)B_*D_*T_];
__device__ __half g_s  [(size_t)B_*T_*T_];
__device__ __half g_y  [M_*D_];
__device__ __half g_h2 [M_*D_];
__device__ __half g_m1 [M_*D_];
__device__ __half g_wqkt[2048*D_];
__device__ __half g_wvt[D_*D_];
__device__ __half g_w1t[D_*D_];
__device__ __half g_w2t[D_*D_];

// ---------------- helpers ------------------------------------------------------
__device__ __forceinline__ uint32_t smem_u32(const void* p) {
    uint32_t a;
    asm("{ .reg .u64 t; cvta.to.shared.u64 t, %1; cvt.u32.u64 %0, t; }" : "=r"(a) : "l"(p));
    return a;
}
__device__ __forceinline__ void cpa16u(uint32_t dst, const void* g) {
    asm volatile("cp.async.cg.shared.global [%0], [%1], 16;" :: "r"(dst), "l"(g));
}
#define CP_COMMIT() asm volatile("cp.async.commit_group;")
#define CP_WAIT2()  asm volatile("cp.async.wait_group 2;")

__device__ __forceinline__ void ldsm4(uint32_t& r0, uint32_t& r1, uint32_t& r2,
                                      uint32_t& r3, uint32_t a) {
    asm volatile("ldmatrix.sync.aligned.m8n8.x4.shared.b16 {%0,%1,%2,%3}, [%4];"
                 : "=r"(r0), "=r"(r1), "=r"(r2), "=r"(r3) : "r"(a));
}
__device__ __forceinline__ void mma_f16(float c[4], uint32_t a0, uint32_t a1,
                                        uint32_t a2, uint32_t a3,
                                        uint32_t b0, uint32_t b1) {
    asm volatile(
        "mma.sync.aligned.m16n8k16.row.col.f32.f16.f16.f32 "
        "{%0,%1,%2,%3}, {%4,%5,%6,%7}, {%8,%9}, {%0,%1,%2,%3};"
        : "+f"(c[0]), "+f"(c[1]), "+f"(c[2]), "+f"(c[3])
        : "r"(a0), "r"(a1), "r"(a2), "r"(a3), "r"(b0), "r"(b1));
}

// ---------------- fused prep: LN1 (blocks 0..M_-1) + weight transpose -----------
struct WT5 { const float* src[5]; __half* dst[5]; };
__global__ void prep_kernel(const float* __restrict__ x, const float* __restrict__ gamma,
                            const float* __restrict__ beta, __half* __restrict__ hout,
                            WT5 wt)
{
    __shared__ float sh[32 * 33];
    const int tid = threadIdx.x;
    if (blockIdx.x < M_) {
        const int row = blockIdx.x;
        const float4* x4 = (const float4*)(x + (size_t)row * D_);
        float4 v = x4[tid];
        float s  = v.x + v.y + v.z + v.w;
        float ss = v.x*v.x + v.y*v.y + v.z*v.z + v.w*v.w;
        #pragma unroll
        for (int o = 16; o; o >>= 1) {
            s  += __shfl_xor_sync(0xffffffffu, s, o);
            ss += __shfl_xor_sync(0xffffffffu, ss, o);
        }
        const int w = tid >> 5;
        if ((tid & 31) == 0) { sh[w] = s; sh[8 + w] = ss; }
        __syncthreads();
        s = 0.f; ss = 0.f;
        #pragma unroll
        for (int k = 0; k < 8; k++) { s += sh[k]; ss += sh[8 + k]; }
        const float mu  = s * (1.0f / D_);
        const float var = (ss - (float)D_ * mu * mu) * (1.0f / (float)(D_ - 1));
        const float cc  = mu * rsqrtf(var);
        __half2* o2 = (__half2*)(hout + (size_t)row * D_);
        const int j = tid * 4;
        o2[2*tid]   = __floats2half2_rn((v.x - cc) * gamma[j]   + beta[j],
                                        (v.y - cc) * gamma[j+1] + beta[j+1]);
        o2[2*tid+1] = __floats2half2_rn((v.z - cc) * gamma[j+2] + beta[j+2],
                                        (v.w - cc) * gamma[j+3] + beta[j+3]);
    } else {
        const int u   = blockIdx.x - M_;
        const int mi  = u >> 10;
        const int rem = u & 1023;
        const int byi = (rem >> 5) * 32;
        const int bxi = (rem & 31) * 32;
        const float* in = wt.src[mi];
        __half* out = wt.dst[mi];
        const float scale = (mi == 0) ? 0.03125f : 1.0f;
        const int tx = tid & 31;
        const int ty = tid >> 5;
        #pragma unroll
        for (int i = 0; i < 32; i += 8)
            sh[(ty + i) * 33 + tx] = in[(size_t)(byi + ty + i) * D_ + bxi + tx] * scale;
        __syncthreads();
        #pragma unroll
        for (int i = 0; i < 32; i += 8)
            out[(size_t)(bxi + ty + i) * D_ + byi + tx] = __float2half_rn(sh[tx * 33 + ty + i]);
    }
}

// ---------------- LayerNorm on half input (LN2), half output --------------------
__global__ void ln_half_kernel(const __half* __restrict__ y, const float* __restrict__ gamma,
                               const float* __restrict__ beta, __half* __restrict__ out)
{
    const int row = blockIdx.x;
    const __half2* y2 = (const __half2*)(y + (size_t)row * D_);
    const int tid = threadIdx.x;
    __half2 h0 = y2[2*tid], h1 = y2[2*tid+1];
    float v0 = __half2float(__low2half(h0)),  v1 = __half2float(__high2half(h0));
    float v2 = __half2float(__low2half(h1)),  v3 = __half2float(__high2half(h1));
    float s  = v0 + v1 + v2 + v3;
    float ss = v0*v0 + v1*v1 + v2*v2 + v3*v3;
    #pragma unroll
    for (int o = 16; o; o >>= 1) {
        s  += __shfl_xor_sync(0xffffffffu, s, o);
        ss += __shfl_xor_sync(0xffffffffu, ss, o);
    }
    __shared__ float sh_s[8], sh_ss[8];
    const int w = tid >> 5;
    if ((tid & 31) == 0) { sh_s[w] = s; sh_ss[w] = ss; }
    __syncthreads();
    s = 0.f; ss = 0.f;
    #pragma unroll
    for (int k = 0; k < 8; k++) { s += sh_s[k]; ss += sh_ss[k]; }
    const float mu  = s * (1.0f / D_);
    const float var = (ss - (float)D_ * mu * mu) * (1.0f / (float)(D_ - 1));
    const float c   = mu * rsqrtf(var);
    __half2* o2 = (__half2*)(out + (size_t)row * D_);
    const int j = tid * 4;
    o2[2*tid]   = __floats2half2_rn((v0 - c) * gamma[j]   + beta[j],
                                    (v1 - c) * gamma[j+1] + beta[j+1]);
    o2[2*tid+1] = __floats2half2_rn((v2 - c) * gamma[j+2] + beta[j+2],
                                    (v3 - c) * gamma[j+3] + beta[j+3]);
}

// ---------------- register-cached causal softmax (1 read + 1 write) -------------
__global__ void softmax_kernel(__half* __restrict__ S)
{
    const int row = blockIdx.x;
    const int b = row >> 11;
    const int q = row & (T_ - 1);
    __half2* r2 = (__half2*)(S + (size_t)b * T_ * T_ + (size_t)q * T_);
    const int n = q + 1;
    const int nh2 = (n + 1) >> 1;
    const int pad2 = (((q >> 7) + 1) << 7) >> 1;
    const int tid = threadIdx.x;

    float2 ex[4];
    float m = -1e30f;
    #pragma unroll
    for (int j = 0; j < 4; j++) {
        const int i = tid + j * 256;
        float2 v = make_float2(-1e30f, -1e30f);
        if (i < nh2) {
            __half2 h = r2[i];
            v.x = __half2float(__low2half(h));
            v.y = (2 * i + 1 < n) ? __half2float(__high2half(h)) : -1e30f;
        }
        ex[j] = v;
        m = fmaxf(m, fmaxf(v.x, v.y));
    }
    #pragma unroll
    for (int o = 16; o; o >>= 1) m = fmaxf(m, __shfl_xor_sync(0xffffffffu, m, o));
    __shared__ float shm[8], shs[8];
    const int w = tid >> 5;
    if ((tid & 31) == 0) shm[w] = m;
    __syncthreads();
    m = shm[0];
    #pragma unroll
    for (int i = 1; i < 8; i++) m = fmaxf(m, shm[i]);

    float s = 0.f;
    #pragma unroll
    for (int j = 0; j < 4; j++) {
        float e0 = (ex[j].x > -1e29f) ? __expf(ex[j].x - m) : 0.f;
        float e1 = (ex[j].y > -1e29f) ? __expf(ex[j].y - m) : 0.f;
        ex[j].x = e0; ex[j].y = e1;
        s += e0 + e1;
    }
    #pragma unroll
    for (int o = 16; o; o >>= 1) s += __shfl_xor_sync(0xffffffffu, s, o);
    if ((tid & 31) == 0) shs[w] = s;
    __syncthreads();
    s = 0.f;
    #pragma unroll
    for (int i = 0; i < 8; i++) s += shs[i];
    const float inv = 1.0f / s;

    #pragma unroll
    for (int j = 0; j < 4; j++) {
        const int i = tid + j * 256;
        if (i < pad2) {
            float2 o = (i < nh2) ? make_float2(ex[j].x * inv, ex[j].y * inv)
                                 : make_float2(0.f, 0.f);
            r2[i] = __floats2half2_rn(o.x, o.y);
        }
    }
}

// ---------------- GEMM tile work descriptor --------------------------------------
struct TileOp {
    const __half* A;      // tile A base (bm applied)
    const __half* Bm;     // tile B base (bn applied)
    void*  C;             // output batch base
    const void* resid;    // residual batch base (or null)
    int lda, ldb, N, nt;
    int bm, bn;
};

// ---------------- persistent fp16 TN GEMM: 4 warps, 64x64 warp tiles -------------
// EPI 0: half(acc); 1: half(relu(acc+bias));
// EPI 3: half(acc + fp32 resid); 4: float acc + bias + half resid
// MODE 0: merged qk+vt schedule; 1: scores lower-triangle; 2: AV cost-sorted;
// MODE 3: plain flattened (mlp)
template<int EPI, int MODE>
__global__ __launch_bounds__(NT, 2)
void hgemm(const __half* __restrict__ A0, const __half* __restrict__ B0, void* Cv,
           const float* __restrict__ bias, const void* __restrict__ resid0,
           int lda, int ldb, int K, int N,
           size_t sA, size_t sB, size_t sC,
           int ntx, int nty, int ntz,
           const __half* A1, const __half* B1, void* Cv1)   // second op (MODE 0)
{
    extern __shared__ char smc[];
    const uint32_t sb = smem_u32(smc);

    const int tid  = threadIdx.x;
    const int lane = tid & 31;
    const int warp = tid >> 5;
    const int g    = lane >> 2;
    const int tq   = lane & 3;
    const int wm   = (warp >> 1) * 64;
    const int wn   = (warp & 1) * 64;
    const int lrow = tid >> 2;
    const int lcc  = tid & 3;

    const uint32_t a_l = (uint32_t)(wm + (lane & 15)) * LDB_S + (uint32_t)(lane >> 4) * 16;
    const uint32_t b_l = (uint32_t)(wn + (lane & 7) + ((lane >> 4) & 1) * 8) * LDB_S
                       + (uint32_t)((lane >> 3) & 1) * 16;

    const int tri = nty * (nty + 1) / 2;
    // MODE 0: op0 = qk (ntx*nty tiles), op1 = vt (16*8*4 = 512 tiles)
    const int ntiles = (MODE == 0) ? (ntx * nty + 512)
                     : (MODE == 1) ? ntz * tri
                     : ntx * nty * ntz;
    const int nsteps = (ntiles + GRID_P - 1) / GRID_P;

    for (int s = 0; s < nsteps; s++) {
        TileOp op;
        if (MODE == 0) {
            const int tile = s * GRID_P + blockIdx.x;
            if (tile >= ntiles) continue;
            if (tile < ntx * nty) {
                const int tx = tile % ntx, ty = tile / ntx;
                op.bm = ty * BM; op.bn = tx * BN;
                op.A = A0 + (size_t)op.bm * lda;
                op.Bm = B0 + (size_t)op.bn * ldb;
                op.C = Cv; op.resid = nullptr;
                op.lda = lda; op.ldb = ldb; op.N = N; op.nt = K / BK;
            } else {
                const int t2 = tile - ntx * nty;     // vt: ntx2=16, nty2=8, ntz2=4
                const int tx = t2 % 16, ty = (t2 / 16) % 8, tz = t2 / 128;
                op.bm = ty * BM; op.bn = tx * BN;
                op.A = A1 + (size_t)op.bm * D_;                       // wvt
                op.Bm = B1 + (size_t)tz * T_ * D_ + (size_t)op.bn * D_; // h batch
                op.C = (__half*)Cv1 + (size_t)tz * D_ * T_;
                op.resid = nullptr;
                op.lda = D_; op.ldb = D_; op.N = T_; op.nt = D_ / BK;
            }
        } else if (MODE == 1) {
            const int tile = s * GRID_P + blockIdx.x;
            if (tile >= ntiles) continue;
            const int tz = tile / tri;
            int t = tile - tz * tri;
            int ty = 0;
            while (t >= ty + 1) { t -= ty + 1; ty++; }
            op.bm = ty * BM; op.bn = t * BN;
            op.A = A0 + (size_t)tz * sA + (size_t)op.bm * lda;
            op.Bm = B0 + (size_t)tz * sB + (size_t)op.bn * ldb;
            op.C = (__half*)Cv + (size_t)tz * sC;
            op.resid = nullptr;
            op.lda = lda; op.ldb = ldb; op.N = N; op.nt = K / BK;
        } else if (MODE == 2) {
            int r = (s == 0) ? (int)blockIdx.x : (2 * GRID_P - 1 - (int)blockIdx.x);
            if (r >= ntiles) continue;
            const int ty = nty - 1 - r / (ntx * ntz);
            const int rem = r % (ntx * ntz);
            const int tz = rem / ntx;
            op.bm = ty * BM; op.bn = (rem % ntx) * BN;
            op.A = A0 + (size_t)tz * sA + (size_t)op.bm * lda;
            op.Bm = B0 + (size_t)tz * sB + (size_t)op.bn * ldb;
            op.C = (__half*)Cv + (size_t)tz * sC;
            op.resid = (const float*)resid0 + (size_t)tz * sC;
            op.lda = lda; op.ldb = ldb; op.N = N; op.nt = op.bm / BK + 4;
        } else {
            const int tile = s * GRID_P + blockIdx.x;
            if (tile >= ntiles) continue;
            const int tx = tile % ntx, ty = tile / ntx;
            op.bm = ty * BM; op.bn = tx * BN;
            op.A = A0 + (size_t)op.bm * lda;
            op.Bm = B0 + (size_t)op.bn * ldb;
            op.C = Cv; op.resid = resid0;
            op.lda = lda; op.ldb = ldb; op.N = N; op.nt = K / BK;
        }

        float c[4][8][4];
        #pragma unroll
        for (int i = 0; i < 4; i++)
            #pragma unroll
            for (int j = 0; j < 8; j++)
                #pragma unroll
                for (int l = 0; l < 4; l++) c[i][j][l] = 0.f;

        __syncthreads();   // protect smem stages from previous tile's readers

        auto load_stage = [&](int buf, int t) {
            const int k0 = t * BK;
            const uint32_t base = sb + buf * STAGE_B;
            #pragma unroll
            for (int p = 0; p < 4; p++) {
                const int r = lrow + p * 32;
                const uint32_t da = base + r * LDB_S + lcc * 16;
                cpa16u(da, op.A + (size_t)r * op.lda + k0 + lcc * 8);
                cpa16u(da + TILE_B, op.Bm + (size_t)r * op.ldb + k0 + lcc * 8);
            }
        };

        // prologue: fill 3 stages
        load_stage(0, 0); CP_COMMIT();
        if (op.nt > 1) { load_stage(1, 1); } CP_COMMIT();
        if (op.nt > 2) { load_stage(2, 2); } CP_COMMIT();

        for (int t = 0; t < op.nt; t++) {
            CP_WAIT2();
            __syncthreads();
            if (t + 3 < op.nt) load_stage((t + 3) % NSTAGE, t + 3);
            CP_COMMIT();

            const uint32_t sbase = sb + (t % NSTAGE) * STAGE_B;
            const uint32_t aaddr = sbase + a_l;
            const uint32_t baddr = sbase + TILE_B + b_l;

            #pragma unroll
            for (int s8 = 0; s8 < 2; s8++) {
                const uint32_t ko = s8 * 32;
                uint32_t af[4][4], bf[4][4];
                #pragma unroll
                for (int mt = 0; mt < 4; mt++)
                    ldsm4(af[mt][0], af[mt][1], af[mt][2], af[mt][3],
                          aaddr + mt * (16 * LDB_S) + ko);
                #pragma unroll
                for (int np = 0; np < 4; np++)
                    ldsm4(bf[np][0], bf[np][1], bf[np][2], bf[np][3],
                          baddr + np * (16 * LDB_S) + ko);
                #pragma unroll
                for (int mt = 0; mt < 4; mt++)
                    #pragma unroll
                    for (int ntl = 0; ntl < 8; ntl++)
                        mma_f16(c[mt][ntl],
                                af[mt][0], af[mt][1], af[mt][2], af[mt][3],
                                bf[ntl >> 1][(ntl & 1) * 2], bf[ntl >> 1][(ntl & 1) * 2 + 1]);
            }
        }

        // ---------------- epilogue ----------------
        __half* Ch = (__half*)op.C;
        float*  Cf = (float*)op.C;
        #pragma unroll
        for (int mt = 0; mt < 4; mt++) {
            #pragma unroll
            for (int ntl = 0; ntl < 8; ntl++) {
                const int col = op.bn + wn + ntl * 8 + 2 * tq;
                float b0 = 0.f, b1 = 0.f;
                if (EPI == 1 || EPI == 4) { b0 = bias[col]; b1 = bias[col + 1]; }
                #pragma unroll
                for (int h = 0; h < 2; h++) {
                    const int row = op.bm + wm + mt * 16 + g + h * 8;
                    float v0 = c[mt][ntl][2 * h], v1 = c[mt][ntl][2 * h + 1];
                    if (EPI == 0) {
                        *(__half2*)&Ch[(size_t)row * op.N + col] = __floats2half2_rn(v0, v1);
                    } else if (EPI == 1) {
                        v0 = fmaxf(v0 + b0, 0.f);
                        v1 = fmaxf(v1 + b1, 0.f);
                        *(__half2*)&Ch[(size_t)row * op.N + col] = __floats2half2_rn(v0, v1);
                    } else if (EPI == 3) {
                        float2 rv = *(const float2*)&((const float*)op.resid)[(size_t)row * op.N + col];
                        *(__half2*)&Ch[(size_t)row * op.N + col] =
                            __floats2half2_rn(v0 + rv.x, v1 + rv.y);
                    } else {
                        __half2 rh = *(const __half2*)&((const __half*)op.resid)[(size_t)row * op.N + col];
                        float2 o;
                        o.x = v0 + b0 + __half2float(__low2half(rh));
                        o.y = v1 + b1 + __half2float(__high2half(rh));
                        *(float2*)&Cf[(size_t)row * op.N + col] = o;
                    }
                }
            }
        }
    }
}

// ---------------- launch --------------------------------------------------------
extern "C" void kernel_launch(void* const* d_in, const int* in_sizes, int n_in,
                              void* d_out, int out_size)
{
    const float* x   = (const float*)d_in[0];
    const float* g1  = (const float*)d_in[1];
    const float* be1 = (const float*)d_in[2];
    const float* wq  = (const float*)d_in[3];
    const float* wk  = (const float*)d_in[4];
    const float* wv  = (const float*)d_in[5];
    const float* g2  = (const float*)d_in[6];
    const float* be2 = (const float*)d_in[7];
    const float* W1  = (const float*)d_in[8];
    const float* b1  = (const float*)d_in[9];
    const float* W2  = (const float*)d_in[10];
    const float* b2  = (const float*)d_in[11];
    float* out = (float*)d_out;

    __half *p_h, *p_qk, *p_vt, *p_s, *p_y, *p_h2, *p_m1;
    __half *p_wqkt, *p_wvt, *p_w1t, *p_w2t;
    cudaGetSymbolAddress((void**)&p_h,    g_h);
    cudaGetSymbolAddress((void**)&p_qk,   g_qk);
    cudaGetSymbolAddress((void**)&p_vt,   g_vt);
    cudaGetSymbolAddress((void**)&p_s,    g_s);
    cudaGetSymbolAddress((void**)&p_y,    g_y);
    cudaGetSymbolAddress((void**)&p_h2,   g_h2);
    cudaGetSymbolAddress((void**)&p_m1,   g_m1);
    cudaGetSymbolAddress((void**)&p_wqkt, g_wqkt);
    cudaGetSymbolAddress((void**)&p_wvt,  g_wvt);
    cudaGetSymbolAddress((void**)&p_w1t,  g_w1t);
    cudaGetSymbolAddress((void**)&p_w2t,  g_w2t);

    cudaFuncSetAttribute(hgemm<0,0>, cudaFuncAttributeMaxDynamicSharedMemorySize, SMEM_B);
    cudaFuncSetAttribute(hgemm<0,1>, cudaFuncAttributeMaxDynamicSharedMemorySize, SMEM_B);
    cudaFuncSetAttribute(hgemm<3,2>, cudaFuncAttributeMaxDynamicSharedMemorySize, SMEM_B);
    cudaFuncSetAttribute(hgemm<1,3>, cudaFuncAttributeMaxDynamicSharedMemorySize, SMEM_B);
    cudaFuncSetAttribute(hgemm<4,3>, cudaFuncAttributeMaxDynamicSharedMemorySize, SMEM_B);

    WT5 wt;
    wt.src[0] = wq; wt.dst[0] = p_wqkt;
    wt.src[1] = wk; wt.dst[1] = p_wqkt + (size_t)1024 * D_;
    wt.src[2] = wv; wt.dst[2] = p_wvt;
    wt.src[3] = W1; wt.dst[3] = p_w1t;
    wt.src[4] = W2; wt.dst[4] = p_w2t;

    // fused LN1 + weight transpose
    prep_kernel<<<M_ + 5 * 1024, 256>>>(x, g1, be1, p_h, wt);

    // merged: qk = h @ [wq/32 | wk] (1024 tiles) + vt = wvt x h (512 tiles)
    hgemm<0,0><<<GRID_P, NT, SMEM_B>>>(p_h, p_wqkt, p_qk, nullptr, nullptr,
                                       D_, D_, D_, 2048, 0, 0, 0, 16, 64, 1,
                                       p_wvt, p_h, p_vt);
    // scores (pre-scaled q): lower triangle only
    hgemm<0,1><<<GRID_P, NT, SMEM_B>>>(p_qk, p_qk + 1024, p_s, nullptr, nullptr,
                                       2048, 2048, D_, T_,
                                       (size_t)T_*2048, (size_t)T_*2048, (size_t)T_*T_,
                                       16, 16, 4, nullptr, nullptr, nullptr);
    softmax_kernel<<<M_, 256>>>(p_s);
    // y = half(P @ V^T + x)  (cost-sorted schedule)
    hgemm<3,2><<<GRID_P, NT, SMEM_B>>>(p_s, p_vt, p_y, nullptr, x,
                                       T_, T_, T_, D_,
                                       (size_t)T_*T_, (size_t)D_*T_, (size_t)T_*D_,
                                       8, 16, 4, nullptr, nullptr, nullptr);
    ln_half_kernel<<<M_, 256>>>(p_y, g2, be2, p_h2);
    hgemm<1,3><<<GRID_P, NT, SMEM_B>>>(p_h2, p_w1t, p_m1, b1, nullptr,
                                       D_, D_, D_, D_, 0, 0, 0, 8, 64, 1,
                                       nullptr, nullptr, nullptr);
    // out = m1 @ W2 + b2 + y (half resid)
    hgemm<4,3><<<GRID_P, NT, SMEM_B>>>(p_m1, p_w2t, out, b2, p_y,
                                       D_, D_, D_, D_, 0, 0, 0, 8, 64, 1,
                                       nullptr, nullptr, nullptr);
}

// round 16
// speedup vs baseline: 1.0035x; 1.0035x over previous
#include <cuda_runtime.h>
#include <cuda_fp16.h>
#include <math.h>
#include <stdint.h>

#define B_ 4
#define T_ 2048
#define D_ 1024
#define M_ (B_*T_)

#define NT 128                  // 4 warps per CTA
#define BM 128
#define BN 128
#define BK 32                   // halves per k-chunk (64 B)
#define LDB_S 80                // bytes per smem row
#define TILE_B (128*LDB_S)      // 10240 B per operand tile
#define STAGE_B (2*TILE_B)      // 20480 B
#define NSTAGE 3
#define SMEM_B (NSTAGE*STAGE_B) // 61440 B
#define GRID_P 304              // persistent CTAs (2 per SM, 152 SMs)

// ---------------- scratch ------------------------------------------------------
__device__ __half g_h  [M_*D_];
__device__ __half g_qk [(size_t)M_*2048];
__device__ __half g_vt [(size_t)B_*D_*T_];
__device__ __half g_s  [(size_t)B_*T_*T_];
__device__ __half g_y  [M_*D_];
__device__ __half g_h2 [M_*D_];
__device__ __half g_m1 [M_*D_];
__device__ __half g_wqkt[2048*D_];
__device__ __half g_wvt[D_*D_];
__device__ __half g_w1t[D_*D_];
__device__ __half g_w2t[D_*D_];

// ---------------- helpers ------------------------------------------------------
__device__ __forceinline__ uint32_t smem_u32(const void* p) {
    uint32_t a;
    asm("{ .reg .u64 t; cvta.to.shared.u64 t, %1; cvt.u32.u64 %0, t; }" : "=r"(a) : "l"(p));
    return a;
}
__device__ __forceinline__ void cpa16u(uint32_t dst, const void* g) {
    asm volatile("cp.async.cg.shared.global [%0], [%1], 16;" :: "r"(dst), "l"(g));
}
#define CP_COMMIT() asm volatile("cp.async.commit_group;")
#define CP_WAIT1()  asm volatile("cp.async.wait_group 1;")

__device__ __forceinline__ void ldsm4(uint32_t& r0, uint32_t& r1, uint32_t& r2,
                                      uint32_t& r3, uint32_t a) {
    asm volatile("ldmatrix.sync.aligned.m8n8.x4.shared.b16 {%0,%1,%2,%3}, [%4];"
                 : "=r"(r0), "=r"(r1), "=r"(r2), "=r"(r3) : "r"(a));
}
__device__ __forceinline__ void mma_f16(float c[4], uint32_t a0, uint32_t a1,
                                        uint32_t a2, uint32_t a3,
                                        uint32_t b0, uint32_t b1) {
    asm volatile(
        "mma.sync.aligned.m16n8k16.row.col.f32.f16.f16.f32 "
        "{%0,%1,%2,%3}, {%4,%5,%6,%7}, {%8,%9}, {%0,%1,%2,%3};"
        : "+f"(c[0]), "+f"(c[1]), "+f"(c[2]), "+f"(c[3])
        : "r"(a0), "r"(a1), "r"(a2), "r"(a3), "r"(b0), "r"(b1));
}

// ---------------- fused prep: LN1 (blocks 0..M_-1) + weight transpose -----------
struct WT5 { const float* src[5]; __half* dst[5]; };
__global__ void prep_kernel(const float* __restrict__ x, const float* __restrict__ gamma,
                            const float* __restrict__ beta, __half* __restrict__ hout,
                            WT5 wt)
{
    __shared__ float sh[32 * 33];
    const int tid = threadIdx.x;
    if (blockIdx.x < M_) {
        const int row = blockIdx.x;
        const float4* x4 = (const float4*)(x + (size_t)row * D_);
        float4 v = x4[tid];
        float s  = v.x + v.y + v.z + v.w;
        float ss = v.x*v.x + v.y*v.y + v.z*v.z + v.w*v.w;
        #pragma unroll
        for (int o = 16; o; o >>= 1) {
            s  += __shfl_xor_sync(0xffffffffu, s, o);
            ss += __shfl_xor_sync(0xffffffffu, ss, o);
        }
        const int w = tid >> 5;
        if ((tid & 31) == 0) { sh[w] = s; sh[8 + w] = ss; }
        __syncthreads();
        s = 0.f; ss = 0.f;
        #pragma unroll
        for (int k = 0; k < 8; k++) { s += sh[k]; ss += sh[8 + k]; }
        const float mu  = s * (1.0f / D_);
        const float var = (ss - (float)D_ * mu * mu) * (1.0f / (float)(D_ - 1));
        const float cc  = mu * rsqrtf(var);
        __half2* o2 = (__half2*)(hout + (size_t)row * D_);
        const int j = tid * 4;
        o2[2*tid]   = __floats2half2_rn((v.x - cc) * gamma[j]   + beta[j],
                                        (v.y - cc) * gamma[j+1] + beta[j+1]);
        o2[2*tid+1] = __floats2half2_rn((v.z - cc) * gamma[j+2] + beta[j+2],
                                        (v.w - cc) * gamma[j+3] + beta[j+3]);
    } else {
        const int u   = blockIdx.x - M_;
        const int mi  = u >> 10;
        const int rem = u & 1023;
        const int byi = (rem >> 5) * 32;
        const int bxi = (rem & 31) * 32;
        const float* in = wt.src[mi];
        __half* out = wt.dst[mi];
        const float scale = (mi == 0) ? 0.03125f : 1.0f;
        const int tx = tid & 31;
        const int ty = tid >> 5;
        #pragma unroll
        for (int i = 0; i < 32; i += 8)
            sh[(ty + i) * 33 + tx] = in[(size_t)(byi + ty + i) * D_ + bxi + tx] * scale;
        __syncthreads();
        #pragma unroll
        for (int i = 0; i < 32; i += 8)
            out[(size_t)(bxi + ty + i) * D_ + byi + tx] = __float2half_rn(sh[tx * 33 + ty + i]);
    }
}

// ---------------- LayerNorm on half input (LN2), half output --------------------
__global__ void ln_half_kernel(const __half* __restrict__ y, const float* __restrict__ gamma,
                               const float* __restrict__ beta, __half* __restrict__ out)
{
    const int row = blockIdx.x;
    const __half2* y2 = (const __half2*)(y + (size_t)row * D_);
    const int tid = threadIdx.x;
    __half2 h0 = y2[2*tid], h1 = y2[2*tid+1];
    float v0 = __half2float(__low2half(h0)),  v1 = __half2float(__high2half(h0));
    float v2 = __half2float(__low2half(h1)),  v3 = __half2float(__high2half(h1));
    float s  = v0 + v1 + v2 + v3;
    float ss = v0*v0 + v1*v1 + v2*v2 + v3*v3;
    #pragma unroll
    for (int o = 16; o; o >>= 1) {
        s  += __shfl_xor_sync(0xffffffffu, s, o);
        ss += __shfl_xor_sync(0xffffffffu, ss, o);
    }
    __shared__ float sh_s[8], sh_ss[8];
    const int w = tid >> 5;
    if ((tid & 31) == 0) { sh_s[w] = s; sh_ss[w] = ss; }
    __syncthreads();
    s = 0.f; ss = 0.f;
    #pragma unroll
    for (int k = 0; k < 8; k++) { s += sh_s[k]; ss += sh_ss[k]; }
    const float mu  = s * (1.0f / D_);
    const float var = (ss - (float)D_ * mu * mu) * (1.0f / (float)(D_ - 1));
    const float c   = mu * rsqrtf(var);
    __half2* o2 = (__half2*)(out + (size_t)row * D_);
    const int j = tid * 4;
    o2[2*tid]   = __floats2half2_rn((v0 - c) * gamma[j]   + beta[j],
                                    (v1 - c) * gamma[j+1] + beta[j+1]);
    o2[2*tid+1] = __floats2half2_rn((v2 - c) * gamma[j+2] + beta[j+2],
                                    (v3 - c) * gamma[j+3] + beta[j+3]);
}

// ---------------- causal softmax: hmax2 max phase, guard-light loops -------------
__global__ void softmax_kernel(__half* __restrict__ S)
{
    const int row = blockIdx.x;
    const int b = row >> 11;
    const int q = row & (T_ - 1);
    __half2* r2 = (__half2*)(S + (size_t)b * T_ * T_ + (size_t)q * T_);
    const int n = q + 1;
    const int nh2 = (n + 1) >> 1;                 // words touching valid region
    const int pad2 = (((q >> 7) + 1) << 7) >> 1;  // words to 128-tile boundary
    const int tid = threadIdx.x;

    // ---- load + max phase (native half2 max; boundary word patched) ----
    const __half NEG = __ushort_as_half(0xFBFFu);        // -57344, < any score
    __half2 vv[4];
    __half2 hm2 = __halves2half2(NEG, NEG);
    #pragma unroll
    for (int j = 0; j < 4; j++) {
        const int i = tid + j * 256;
        __half2 h = __halves2half2(NEG, NEG);
        if (i < nh2) {
            h = r2[i];
            if (2 * i + 1 >= n) h = __halves2half2(__low2half(h), NEG);  // odd-n boundary
        }
        vv[j] = h;
        hm2 = __hmax2(hm2, h);
    }
    float m = fmaxf(__half2float(__low2half(hm2)), __half2float(__high2half(hm2)));
    #pragma unroll
    for (int o = 16; o; o >>= 1) m = fmaxf(m, __shfl_xor_sync(0xffffffffu, m, o));
    __shared__ float shm[8], shs[8];
    const int w = tid >> 5;
    if ((tid & 31) == 0) shm[w] = m;
    __syncthreads();
    m = shm[0];
    #pragma unroll
    for (int i = 1; i < 8; i++) m = fmaxf(m, shm[i]);

    // ---- exp + sum (invalid lanes hold NEG -> exp ~ 0 exactly after max-sub) ----
    float2 ex[4];
    float s = 0.f;
    #pragma unroll
    for (int j = 0; j < 4; j++) {
        float e0 = __expf(__half2float(__low2half(vv[j]))  - m);
        float e1 = __expf(__half2float(__high2half(vv[j])) - m);
        // NEG lanes: exp(-57344 - m) == 0.0f in fp32 — no guard needed
        ex[j].x = e0; ex[j].y = e1;
        s += e0 + e1;
    }
    #pragma unroll
    for (int o = 16; o; o >>= 1) s += __shfl_xor_sync(0xffffffffu, s, o);
    if ((tid & 31) == 0) shs[w] = s;
    __syncthreads();
    s = 0.f;
    #pragma unroll
    for (int i = 0; i < 8; i++) s += shs[i];
    const float inv = 1.0f / s;

    // ---- write (valid words get p; pad words get 0 — NEG lanes already 0) ----
    #pragma unroll
    for (int j = 0; j < 4; j++) {
        const int i = tid + j * 256;
        if (i < pad2)
            r2[i] = __floats2half2_rn(ex[j].x * inv, ex[j].y * inv);
    }
}

// ---------------- persistent fp16 TN GEMM: 4 warps, 64x64 warp tiles -------------
// EPI 0: half(acc); 1: half(relu(acc+bias));
// EPI 3: half(acc + fp32 resid); 4: float acc + bias + half resid
// MODE 0: plain flattened (z,y,x); 1: scores lower-triangle;
// MODE 2: AV (k bound at bm+128), cost-sorted heavy-first schedule
template<int EPI, int MODE>
__global__ __launch_bounds__(NT, 2)
void hgemm(const __half* __restrict__ A0, const __half* __restrict__ B0, void* Cv,
           const float* __restrict__ bias, const void* __restrict__ resid0,
           int lda, int ldb, int K, int N,
           size_t sA, size_t sB, size_t sC,
           int ntx, int nty, int ntz)
{
    extern __shared__ char smc[];
    const uint32_t sb = smem_u32(smc);

    const int tid  = threadIdx.x;
    const int lane = tid & 31;
    const int warp = tid >> 5;
    const int g    = lane >> 2;
    const int tq   = lane & 3;
    const int wm   = (warp >> 1) * 64;
    const int wn   = (warp & 1) * 64;
    const int lrow = tid >> 2;
    const int lcc  = tid & 3;

    const uint32_t a_l = (uint32_t)(wm + (lane & 15)) * LDB_S + (uint32_t)(lane >> 4) * 16;
    const uint32_t b_l = (uint32_t)(wn + (lane & 7) + ((lane >> 4) & 1) * 8) * LDB_S
                       + (uint32_t)((lane >> 3) & 1) * 16;

    const int tri = nty * (nty + 1) / 2;
    const int ntiles = (MODE == 1) ? ntz * tri : ntx * nty * ntz;
    const int nsteps = (ntiles + GRID_P - 1) / GRID_P;

    for (int s = 0; s < nsteps; s++) {
        int tx, ty, tz;
        if (MODE == 2) {
            int r = (s == 0) ? (int)blockIdx.x : (2 * GRID_P - 1 - (int)blockIdx.x);
            if (r >= ntiles) continue;
            ty = nty - 1 - r / (ntx * ntz);
            const int rem = r % (ntx * ntz);
            tz = rem / ntx;
            tx = rem % ntx;
        } else if (MODE == 1) {
            const int tile = s * GRID_P + blockIdx.x;
            if (tile >= ntiles) continue;
            tz = tile / tri;
            int t = tile - tz * tri;
            ty = 0;
            while (t >= ty + 1) { t -= ty + 1; ty++; }
            tx = t;
        } else {
            const int tile = s * GRID_P + blockIdx.x;
            if (tile >= ntiles) continue;
            tx = tile % ntx;
            ty = (tile / ntx) % nty;
            tz = tile / (ntx * nty);
        }
        const int bm = ty * BM;
        const int bn = tx * BN;

        const __half* A  = A0 + (size_t)tz * sA + (size_t)bm * lda;
        const __half* Bm = B0 + (size_t)tz * sB + (size_t)bn * ldb;
        __half* Ch = (__half*)Cv + (size_t)tz * sC;
        float*  Cf = (float*)Cv  + (size_t)tz * sC;
        const float*  residf = resid0 ? (const float*)resid0  + (size_t)tz * sC : nullptr;
        const __half* residh = resid0 ? (const __half*)resid0 + (size_t)tz * sC : nullptr;

        float c[4][8][4];
        #pragma unroll
        for (int i = 0; i < 4; i++)
            #pragma unroll
            for (int j = 0; j < 8; j++)
                #pragma unroll
                for (int l = 0; l < 4; l++) c[i][j][l] = 0.f;

        const int nt = (MODE == 2) ? (bm / BK + 4) : (K / BK);

        __syncthreads();

        auto load_stage = [&](int buf, int t) {
            const int k0 = t * BK;
            const uint32_t base = sb + buf * STAGE_B;
            #pragma unroll
            for (int p = 0; p < 4; p++) {
                const int r = lrow + p * 32;
                const uint32_t da = base + r * LDB_S + lcc * 16;
                cpa16u(da, A + (size_t)r * lda + k0 + lcc * 8);
                cpa16u(da + TILE_B, Bm + (size_t)r * ldb + k0 + lcc * 8);
            }
        };

        load_stage(0, 0); CP_COMMIT();
        load_stage(1, 1); CP_COMMIT();

        for (int t = 0; t < nt; t++) {
            CP_WAIT1();
            __syncthreads();
            if (t + 2 < nt) load_stage((t + 2) % NSTAGE, t + 2);
            CP_COMMIT();

            const uint32_t sbase = sb + (t % NSTAGE) * STAGE_B;
            const uint32_t aaddr = sbase + a_l;
            const uint32_t baddr = sbase + TILE_B + b_l;

            #pragma unroll
            for (int s8 = 0; s8 < 2; s8++) {
                const uint32_t ko = s8 * 32;
                uint32_t af[4][4], bf[4][4];
                #pragma unroll
                for (int mt = 0; mt < 4; mt++)
                    ldsm4(af[mt][0], af[mt][1], af[mt][2], af[mt][3],
                          aaddr + mt * (16 * LDB_S) + ko);
                #pragma unroll
                for (int np = 0; np < 4; np++)
                    ldsm4(bf[np][0], bf[np][1], bf[np][2], bf[np][3],
                          baddr + np * (16 * LDB_S) + ko);
                #pragma unroll
                for (int mt = 0; mt < 4; mt++)
                    #pragma unroll
                    for (int ntl = 0; ntl < 8; ntl++)
                        mma_f16(c[mt][ntl],
                                af[mt][0], af[mt][1], af[mt][2], af[mt][3],
                                bf[ntl >> 1][(ntl & 1) * 2], bf[ntl >> 1][(ntl & 1) * 2 + 1]);
            }
        }

        // ---------------- epilogue ----------------
        #pragma unroll
        for (int mt = 0; mt < 4; mt++) {
            #pragma unroll
            for (int ntl = 0; ntl < 8; ntl++) {
                const int col = bn + wn + ntl * 8 + 2 * tq;
                float b0 = 0.f, b1 = 0.f;
                if (EPI == 1 || EPI == 4) { b0 = bias[col]; b1 = bias[col + 1]; }
                #pragma unroll
                for (int h = 0; h < 2; h++) {
                    const int row = bm + wm + mt * 16 + g + h * 8;
                    float v0 = c[mt][ntl][2 * h], v1 = c[mt][ntl][2 * h + 1];
                    if (EPI == 0) {
                        *(__half2*)&Ch[(size_t)row * N + col] = __floats2half2_rn(v0, v1);
                    } else if (EPI == 1) {
                        v0 = fmaxf(v0 + b0, 0.f);
                        v1 = fmaxf(v1 + b1, 0.f);
                        *(__half2*)&Ch[(size_t)row * N + col] = __floats2half2_rn(v0, v1);
                    } else if (EPI == 3) {
                        float2 rv = *(const float2*)&residf[(size_t)row * N + col];
                        *(__half2*)&Ch[(size_t)row * N + col] =
                            __floats2half2_rn(v0 + rv.x, v1 + rv.y);
                    } else {
                        __half2 rh = *(const __half2*)&residh[(size_t)row * N + col];
                        float2 o;
                        o.x = v0 + b0 + __half2float(__low2half(rh));
                        o.y = v1 + b1 + __half2float(__high2half(rh));
                        *(float2*)&Cf[(size_t)row * N + col] = o;
                    }
                }
            }
        }
    }
}

// ---------------- launch --------------------------------------------------------
extern "C" void kernel_launch(void* const* d_in, const int* in_sizes, int n_in,
                              void* d_out, int out_size)
{
    const float* x   = (const float*)d_in[0];
    const float* g1  = (const float*)d_in[1];
    const float* be1 = (const float*)d_in[2];
    const float* wq  = (const float*)d_in[3];
    const float* wk  = (const float*)d_in[4];
    const float* wv  = (const float*)d_in[5];
    const float* g2  = (const float*)d_in[6];
    const float* be2 = (const float*)d_in[7];
    const float* W1  = (const float*)d_in[8];
    const float* b1  = (const float*)d_in[9];
    const float* W2  = (const float*)d_in[10];
    const float* b2  = (const float*)d_in[11];
    float* out = (float*)d_out;

    __half *p_h, *p_qk, *p_vt, *p_s, *p_y, *p_h2, *p_m1;
    __half *p_wqkt, *p_wvt, *p_w1t, *p_w2t;
    cudaGetSymbolAddress((void**)&p_h,    g_h);
    cudaGetSymbolAddress((void**)&p_qk,   g_qk);
    cudaGetSymbolAddress((void**)&p_vt,   g_vt);
    cudaGetSymbolAddress((void**)&p_s,    g_s);
    cudaGetSymbolAddress((void**)&p_y,    g_y);
    cudaGetSymbolAddress((void**)&p_h2,   g_h2);
    cudaGetSymbolAddress((void**)&p_m1,   g_m1);
    cudaGetSymbolAddress((void**)&p_wqkt, g_wqkt);
    cudaGetSymbolAddress((void**)&p_wvt,  g_wvt);
    cudaGetSymbolAddress((void**)&p_w1t,  g_w1t);
    cudaGetSymbolAddress((void**)&p_w2t,  g_w2t);

    cudaFuncSetAttribute(hgemm<0,0>, cudaFuncAttributeMaxDynamicSharedMemorySize, SMEM_B);
    cudaFuncSetAttribute(hgemm<1,0>, cudaFuncAttributeMaxDynamicSharedMemorySize, SMEM_B);
    cudaFuncSetAttribute(hgemm<4,0>, cudaFuncAttributeMaxDynamicSharedMemorySize, SMEM_B);
    cudaFuncSetAttribute(hgemm<0,1>, cudaFuncAttributeMaxDynamicSharedMemorySize, SMEM_B);
    cudaFuncSetAttribute(hgemm<3,2>, cudaFuncAttributeMaxDynamicSharedMemorySize, SMEM_B);

    WT5 wt;
    wt.src[0] = wq; wt.dst[0] = p_wqkt;
    wt.src[1] = wk; wt.dst[1] = p_wqkt + (size_t)1024 * D_;
    wt.src[2] = wv; wt.dst[2] = p_wvt;
    wt.src[3] = W1; wt.dst[3] = p_w1t;
    wt.src[4] = W2; wt.dst[4] = p_w2t;

    // fused LN1 + weight transpose
    prep_kernel<<<M_ + 5 * 1024, 256>>>(x, g1, be1, p_h, wt);

    // qk = h @ [wq/32 | wk]   (N=2048)
    hgemm<0,0><<<GRID_P, NT, SMEM_B>>>(p_h, p_wqkt, p_qk, nullptr, nullptr,
                                       D_, D_, D_, 2048, 0, 0, 0, 16, 64, 1);
    // vt[b][d][t] = wvt[d][:] . h[b*T+t][:]
    hgemm<0,0><<<GRID_P, NT, SMEM_B>>>(p_wvt, p_h, p_vt, nullptr, nullptr,
                                       D_, D_, D_, T_, 0, (size_t)T_*D_, (size_t)D_*T_,
                                       16, 8, 4);
    // scores (pre-scaled q): lower triangle only
    hgemm<0,1><<<GRID_P, NT, SMEM_B>>>(p_qk, p_qk + 1024, p_s, nullptr, nullptr,
                                       2048, 2048, D_, T_,
                                       (size_t)T_*2048, (size_t)T_*2048, (size_t)T_*T_,
                                       16, 16, 4);
    softmax_kernel<<<M_, 256>>>(p_s);
    // y = half(P @ V^T + x)  (cost-sorted schedule)
    hgemm<3,2><<<GRID_P, NT, SMEM_B>>>(p_s, p_vt, p_y, nullptr, x,
                                       T_, T_, T_, D_,
                                       (size_t)T_*T_, (size_t)D_*T_, (size_t)T_*D_,
                                       8, 16, 4);
    ln_half_kernel<<<M_, 256>>>(p_y, g2, be2, p_h2);
    hgemm<1,0><<<GRID_P, NT, SMEM_B>>>(p_h2, p_w1t, p_m1, b1, nullptr,
                                       D_, D_, D_, D_, 0, 0, 0, 8, 64, 1);
    // out = m1 @ W2 + b2 + y (half resid)
    hgemm<4,0><<<GRID_P, NT, SMEM_B>>>(p_m1, p_w2t, out, b2, p_y,
                                       D_, D_, D_, D_, 0, 0, 0, 8, 64, 1);
}

// round 17
// speedup vs baseline: 1.0159x; 1.0124x over previous
#include <cuda_runtime.h>
#include <cuda_fp16.h>
#include <math.h>
#include <stdint.h>

#define B_ 4
#define T_ 2048
#define D_ 1024
#define M_ (B_*T_)

#define NT 128                  // 4 warps per CTA
#define BM 128
#define BN 128
#define BK 32                   // halves per k-chunk (64 B)
#define LDB_S 80                // bytes per smem row
#define TILE_B (128*LDB_S)      // 10240 B per operand tile
#define STAGE_B (2*TILE_B)      // 20480 B
#define NSTAGE 3
#define SMEM_B (NSTAGE*STAGE_B) // 61440 B
#define GRID_P 304              // persistent CTAs (scores/AV/mlp)

// ---------------- scratch ------------------------------------------------------
__device__ __half g_h  [M_*D_];
__device__ __half g_qk [(size_t)M_*2048];
__device__ __half g_vt [(size_t)B_*D_*T_];
__device__ __half g_s  [(size_t)B_*T_*T_];
__device__ __half g_y  [M_*D_];
__device__ __half g_h2 [M_*D_];
__device__ __half g_m1 [M_*D_];
__device__ __half g_wqkt[2048*D_];
__device__ __half g_wvt[D_*D_];
__device__ __half g_w1t[D_*D_];
__device__ __half g_w2t[D_*D_];

// ---------------- helpers ------------------------------------------------------
__device__ __forceinline__ uint32_t smem_u32(const void* p) {
    uint32_t a;
    asm("{ .reg .u64 t; cvta.to.shared.u64 t, %1; cvt.u32.u64 %0, t; }" : "=r"(a) : "l"(p));
    return a;
}
__device__ __forceinline__ void cpa16u(uint32_t dst, const void* g) {
    asm volatile("cp.async.cg.shared.global [%0], [%1], 16;" :: "r"(dst), "l"(g));
}
#define CP_COMMIT() asm volatile("cp.async.commit_group;")
#define CP_WAIT1()  asm volatile("cp.async.wait_group 1;")

__device__ __forceinline__ void ldsm4(uint32_t& r0, uint32_t& r1, uint32_t& r2,
                                      uint32_t& r3, uint32_t a) {
    asm volatile("ldmatrix.sync.aligned.m8n8.x4.shared.b16 {%0,%1,%2,%3}, [%4];"
                 : "=r"(r0), "=r"(r1), "=r"(r2), "=r"(r3) : "r"(a));
}
__device__ __forceinline__ void mma_f16(float c[4], uint32_t a0, uint32_t a1,
                                        uint32_t a2, uint32_t a3,
                                        uint32_t b0, uint32_t b1) {
    asm volatile(
        "mma.sync.aligned.m16n8k16.row.col.f32.f16.f16.f32 "
        "{%0,%1,%2,%3}, {%4,%5,%6,%7}, {%8,%9}, {%0,%1,%2,%3};"
        : "+f"(c[0]), "+f"(c[1]), "+f"(c[2]), "+f"(c[3])
        : "r"(a0), "r"(a1), "r"(a2), "r"(a3), "r"(b0), "r"(b1));
}

// ---------------- fused prep: LN1 (blocks 0..M_-1) + weight transpose -----------
struct WT5 { const float* src[5]; __half* dst[5]; };
__global__ void prep_kernel(const float* __restrict__ x, const float* __restrict__ gamma,
                            const float* __restrict__ beta, __half* __restrict__ hout,
                            WT5 wt)
{
    __shared__ float sh[32 * 33];
    const int tid = threadIdx.x;
    if (blockIdx.x < M_) {
        const int row = blockIdx.x;
        const float4* x4 = (const float4*)(x + (size_t)row * D_);
        float4 v = x4[tid];
        float s  = v.x + v.y + v.z + v.w;
        float ss = v.x*v.x + v.y*v.y + v.z*v.z + v.w*v.w;
        #pragma unroll
        for (int o = 16; o; o >>= 1) {
            s  += __shfl_xor_sync(0xffffffffu, s, o);
            ss += __shfl_xor_sync(0xffffffffu, ss, o);
        }
        const int w = tid >> 5;
        if ((tid & 31) == 0) { sh[w] = s; sh[8 + w] = ss; }
        __syncthreads();
        s = 0.f; ss = 0.f;
        #pragma unroll
        for (int k = 0; k < 8; k++) { s += sh[k]; ss += sh[8 + k]; }
        const float mu  = s * (1.0f / D_);
        const float var = (ss - (float)D_ * mu * mu) * (1.0f / (float)(D_ - 1));
        const float cc  = mu * rsqrtf(var);
        __half2* o2 = (__half2*)(hout + (size_t)row * D_);
        const int j = tid * 4;
        o2[2*tid]   = __floats2half2_rn((v.x - cc) * gamma[j]   + beta[j],
                                        (v.y - cc) * gamma[j+1] + beta[j+1]);
        o2[2*tid+1] = __floats2half2_rn((v.z - cc) * gamma[j+2] + beta[j+2],
                                        (v.w - cc) * gamma[j+3] + beta[j+3]);
    } else {
        const int u   = blockIdx.x - M_;
        const int mi  = u >> 10;
        const int rem = u & 1023;
        const int byi = (rem >> 5) * 32;
        const int bxi = (rem & 31) * 32;
        const float* in = wt.src[mi];
        __half* out = wt.dst[mi];
        const float scale = (mi == 0) ? 0.03125f : 1.0f;
        const int tx = tid & 31;
        const int ty = tid >> 5;
        #pragma unroll
        for (int i = 0; i < 32; i += 8)
            sh[(ty + i) * 33 + tx] = in[(size_t)(byi + ty + i) * D_ + bxi + tx] * scale;
        __syncthreads();
        #pragma unroll
        for (int i = 0; i < 32; i += 8)
            out[(size_t)(bxi + ty + i) * D_ + byi + tx] = __float2half_rn(sh[tx * 33 + ty + i]);
    }
}

// ---------------- LayerNorm on half input (LN2), half output --------------------
__global__ void ln_half_kernel(const __half* __restrict__ y, const float* __restrict__ gamma,
                               const float* __restrict__ beta, __half* __restrict__ out)
{
    const int row = blockIdx.x;
    const __half2* y2 = (const __half2*)(y + (size_t)row * D_);
    const int tid = threadIdx.x;
    __half2 h0 = y2[2*tid], h1 = y2[2*tid+1];
    float v0 = __half2float(__low2half(h0)),  v1 = __half2float(__high2half(h0));
    float v2 = __half2float(__low2half(h1)),  v3 = __half2float(__high2half(h1));
    float s  = v0 + v1 + v2 + v3;
    float ss = v0*v0 + v1*v1 + v2*v2 + v3*v3;
    #pragma unroll
    for (int o = 16; o; o >>= 1) {
        s  += __shfl_xor_sync(0xffffffffu, s, o);
        ss += __shfl_xor_sync(0xffffffffu, ss, o);
    }
    __shared__ float sh_s[8], sh_ss[8];
    const int w = tid >> 5;
    if ((tid & 31) == 0) { sh_s[w] = s; sh_ss[w] = ss; }
    __syncthreads();
    s = 0.f; ss = 0.f;
    #pragma unroll
    for (int k = 0; k < 8; k++) { s += sh_s[k]; ss += sh_ss[k]; }
    const float mu  = s * (1.0f / D_);
    const float var = (ss - (float)D_ * mu * mu) * (1.0f / (float)(D_ - 1));
    const float c   = mu * rsqrtf(var);
    __half2* o2 = (__half2*)(out + (size_t)row * D_);
    const int j = tid * 4;
    o2[2*tid]   = __floats2half2_rn((v0 - c) * gamma[j]   + beta[j],
                                    (v1 - c) * gamma[j+1] + beta[j+1]);
    o2[2*tid+1] = __floats2half2_rn((v2 - c) * gamma[j+2] + beta[j+2],
                                    (v3 - c) * gamma[j+3] + beta[j+3]);
}

// ---------------- causal softmax: hmax2 max phase, guard-light loops -------------
__global__ void softmax_kernel(__half* __restrict__ S)
{
    const int row = blockIdx.x;
    const int b = row >> 11;
    const int q = row & (T_ - 1);
    __half2* r2 = (__half2*)(S + (size_t)b * T_ * T_ + (size_t)q * T_);
    const int n = q + 1;
    const int nh2 = (n + 1) >> 1;
    const int pad2 = (((q >> 7) + 1) << 7) >> 1;
    const int tid = threadIdx.x;

    const __half NEG = __ushort_as_half(0xFBFFu);        // -57344
    __half2 vv[4];
    __half2 hm2 = __halves2half2(NEG, NEG);
    #pragma unroll
    for (int j = 0; j < 4; j++) {
        const int i = tid + j * 256;
        __half2 h = __halves2half2(NEG, NEG);
        if (i < nh2) {
            h = r2[i];
            if (2 * i + 1 >= n) h = __halves2half2(__low2half(h), NEG);
        }
        vv[j] = h;
        hm2 = __hmax2(hm2, h);
    }
    float m = fmaxf(__half2float(__low2half(hm2)), __half2float(__high2half(hm2)));
    #pragma unroll
    for (int o = 16; o; o >>= 1) m = fmaxf(m, __shfl_xor_sync(0xffffffffu, m, o));
    __shared__ float shm[8], shs[8];
    const int w = tid >> 5;
    if ((tid & 31) == 0) shm[w] = m;
    __syncthreads();
    m = shm[0];
    #pragma unroll
    for (int i = 1; i < 8; i++) m = fmaxf(m, shm[i]);

    float2 ex[4];
    float s = 0.f;
    #pragma unroll
    for (int j = 0; j < 4; j++) {
        float e0 = __expf(__half2float(__low2half(vv[j]))  - m);
        float e1 = __expf(__half2float(__high2half(vv[j])) - m);
        ex[j].x = e0; ex[j].y = e1;
        s += e0 + e1;
    }
    #pragma unroll
    for (int o = 16; o; o >>= 1) s += __shfl_xor_sync(0xffffffffu, s, o);
    if ((tid & 31) == 0) shs[w] = s;
    __syncthreads();
    s = 0.f;
    #pragma unroll
    for (int i = 0; i < 8; i++) s += shs[i];
    const float inv = 1.0f / s;

    #pragma unroll
    for (int j = 0; j < 4; j++) {
        const int i = tid + j * 256;
        if (i < pad2)
            r2[i] = __floats2half2_rn(ex[j].x * inv, ex[j].y * inv);
    }
}

// ---------------- fp16 TN GEMM: 4 warps, 64x64 warp tiles -----------------------
// EPI 0: half(acc); 1: half(relu(acc+bias));
// EPI 3: half(acc + fp32 resid); 4: float acc + bias + half resid
// MODE 0: plain flattened (z,y,x), grid-stride; 1: scores lower-triangle;
// MODE 2: AV (k bound at bm+128), cost-sorted heavy-first schedule
template<int EPI, int MODE>
__global__ __launch_bounds__(NT, 2)
void hgemm(const __half* __restrict__ A0, const __half* __restrict__ B0, void* Cv,
           const float* __restrict__ bias, const void* __restrict__ resid0,
           int lda, int ldb, int K, int N,
           size_t sA, size_t sB, size_t sC,
           int ntx, int nty, int ntz)
{
    extern __shared__ char smc[];
    const uint32_t sb = smem_u32(smc);

    const int tid  = threadIdx.x;
    const int lane = tid & 31;
    const int warp = tid >> 5;
    const int g    = lane >> 2;
    const int tq   = lane & 3;
    const int wm   = (warp >> 1) * 64;
    const int wn   = (warp & 1) * 64;
    const int lrow = tid >> 2;
    const int lcc  = tid & 3;

    const uint32_t a_l = (uint32_t)(wm + (lane & 15)) * LDB_S + (uint32_t)(lane >> 4) * 16;
    const uint32_t b_l = (uint32_t)(wn + (lane & 7) + ((lane >> 4) & 1) * 8) * LDB_S
                       + (uint32_t)((lane >> 3) & 1) * 16;

    const int tri = nty * (nty + 1) / 2;
    const int ntiles = (MODE == 1) ? ntz * tri : ntx * nty * ntz;
    const int gsz = (int)gridDim.x;
    const int nsteps = (ntiles + gsz - 1) / gsz;

    for (int s = 0; s < nsteps; s++) {
        int tx, ty, tz;
        if (MODE == 2) {
            int r = (s == 0) ? (int)blockIdx.x : (2 * gsz - 1 - (int)blockIdx.x);
            if (r >= ntiles) continue;
            ty = nty - 1 - r / (ntx * ntz);
            const int rem = r % (ntx * ntz);
            tz = rem / ntx;
            tx = rem % ntx;
        } else if (MODE == 1) {
            const int tile = s * gsz + blockIdx.x;
            if (tile >= ntiles) continue;
            tz = tile / tri;
            int t = tile - tz * tri;
            ty = 0;
            while (t >= ty + 1) { t -= ty + 1; ty++; }
            tx = t;
        } else {
            const int tile = s * gsz + blockIdx.x;
            if (tile >= ntiles) continue;
            tx = tile % ntx;
            ty = (tile / ntx) % nty;
            tz = tile / (ntx * nty);
        }
        const int bm = ty * BM;
        const int bn = tx * BN;

        const __half* A  = A0 + (size_t)tz * sA + (size_t)bm * lda;
        const __half* Bm = B0 + (size_t)tz * sB + (size_t)bn * ldb;
        __half* Ch = (__half*)Cv + (size_t)tz * sC;
        float*  Cf = (float*)Cv  + (size_t)tz * sC;
        const float*  residf = resid0 ? (const float*)resid0  + (size_t)tz * sC : nullptr;
        const __half* residh = resid0 ? (const __half*)resid0 + (size_t)tz * sC : nullptr;

        float c[4][8][4];
        #pragma unroll
        for (int i = 0; i < 4; i++)
            #pragma unroll
            for (int j = 0; j < 8; j++)
                #pragma unroll
                for (int l = 0; l < 4; l++) c[i][j][l] = 0.f;

        const int nt = (MODE == 2) ? (bm / BK + 4) : (K / BK);

        __syncthreads();

        auto load_stage = [&](int buf, int t) {
            const int k0 = t * BK;
            const uint32_t base = sb + buf * STAGE_B;
            #pragma unroll
            for (int p = 0; p < 4; p++) {
                const int r = lrow + p * 32;
                const uint32_t da = base + r * LDB_S + lcc * 16;
                cpa16u(da, A + (size_t)r * lda + k0 + lcc * 8);
                cpa16u(da + TILE_B, Bm + (size_t)r * ldb + k0 + lcc * 8);
            }
        };

        load_stage(0, 0); CP_COMMIT();
        load_stage(1, 1); CP_COMMIT();

        for (int t = 0; t < nt; t++) {
            CP_WAIT1();
            __syncthreads();
            if (t + 2 < nt) load_stage((t + 2) % NSTAGE, t + 2);
            CP_COMMIT();

            const uint32_t sbase = sb + (t % NSTAGE) * STAGE_B;
            const uint32_t aaddr = sbase + a_l;
            const uint32_t baddr = sbase + TILE_B + b_l;

            #pragma unroll
            for (int s8 = 0; s8 < 2; s8++) {
                const uint32_t ko = s8 * 32;
                uint32_t af[4][4], bf[4][4];
                #pragma unroll
                for (int mt = 0; mt < 4; mt++)
                    ldsm4(af[mt][0], af[mt][1], af[mt][2], af[mt][3],
                          aaddr + mt * (16 * LDB_S) + ko);
                #pragma unroll
                for (int np = 0; np < 4; np++)
                    ldsm4(bf[np][0], bf[np][1], bf[np][2], bf[np][3],
                          baddr + np * (16 * LDB_S) + ko);
                #pragma unroll
                for (int mt = 0; mt < 4; mt++)
                    #pragma unroll
                    for (int ntl = 0; ntl < 8; ntl++)
                        mma_f16(c[mt][ntl],
                                af[mt][0], af[mt][1], af[mt][2], af[mt][3],
                                bf[ntl >> 1][(ntl & 1) * 2], bf[ntl >> 1][(ntl & 1) * 2 + 1]);
            }
        }

        // ---------------- epilogue ----------------
        #pragma unroll
        for (int mt = 0; mt < 4; mt++) {
            #pragma unroll
            for (int ntl = 0; ntl < 8; ntl++) {
                const int col = bn + wn + ntl * 8 + 2 * tq;
                float b0 = 0.f, b1 = 0.f;
                if (EPI == 1 || EPI == 4) { b0 = bias[col]; b1 = bias[col + 1]; }
                #pragma unroll
                for (int h = 0; h < 2; h++) {
                    const int row = bm + wm + mt * 16 + g + h * 8;
                    float v0 = c[mt][ntl][2 * h], v1 = c[mt][ntl][2 * h + 1];
                    if (EPI == 0) {
                        *(__half2*)&Ch[(size_t)row * N + col] = __floats2half2_rn(v0, v1);
                    } else if (EPI == 1) {
                        v0 = fmaxf(v0 + b0, 0.f);
                        v1 = fmaxf(v1 + b1, 0.f);
                        *(__half2*)&Ch[(size_t)row * N + col] = __floats2half2_rn(v0, v1);
                    } else if (EPI == 3) {
                        float2 rv = *(const float2*)&residf[(size_t)row * N + col];
                        *(__half2*)&Ch[(size_t)row * N + col] =
                            __floats2half2_rn(v0 + rv.x, v1 + rv.y);
                    } else {
                        __half2 rh = *(const __half2*)&residh[(size_t)row * N + col];
                        float2 o;
                        o.x = v0 + b0 + __half2float(__low2half(rh));
                        o.y = v1 + b1 + __half2float(__high2half(rh));
                        *(float2*)&Cf[(size_t)row * N + col] = o;
                    }
                }
            }
        }
    }
}

// ---------------- launch --------------------------------------------------------
extern "C" void kernel_launch(void* const* d_in, const int* in_sizes, int n_in,
                              void* d_out, int out_size)
{
    const float* x   = (const float*)d_in[0];
    const float* g1  = (const float*)d_in[1];
    const float* be1 = (const float*)d_in[2];
    const float* wq  = (const float*)d_in[3];
    const float* wk  = (const float*)d_in[4];
    const float* wv  = (const float*)d_in[5];
    const float* g2  = (const float*)d_in[6];
    const float* be2 = (const float*)d_in[7];
    const float* W1  = (const float*)d_in[8];
    const float* b1  = (const float*)d_in[9];
    const float* W2  = (const float*)d_in[10];
    const float* b2  = (const float*)d_in[11];
    float* out = (float*)d_out;

    __half *p_h, *p_qk, *p_vt, *p_s, *p_y, *p_h2, *p_m1;
    __half *p_wqkt, *p_wvt, *p_w1t, *p_w2t;
    cudaGetSymbolAddress((void**)&p_h,    g_h);
    cudaGetSymbolAddress((void**)&p_qk,   g_qk);
    cudaGetSymbolAddress((void**)&p_vt,   g_vt);
    cudaGetSymbolAddress((void**)&p_s,    g_s);
    cudaGetSymbolAddress((void**)&p_y,    g_y);
    cudaGetSymbolAddress((void**)&p_h2,   g_h2);
    cudaGetSymbolAddress((void**)&p_m1,   g_m1);
    cudaGetSymbolAddress((void**)&p_wqkt, g_wqkt);
    cudaGetSymbolAddress((void**)&p_wvt,  g_wvt);
    cudaGetSymbolAddress((void**)&p_w1t,  g_w1t);
    cudaGetSymbolAddress((void**)&p_w2t,  g_w2t);

    // one-time resources (created on the uncaptured correctness call)
    static cudaStream_t s1 = nullptr;
    static cudaEvent_t ev_fork = nullptr, ev_join = nullptr;
    static bool init_done = false;
    if (!init_done) {
        cudaStreamCreateWithFlags(&s1, cudaStreamNonBlocking);
        cudaEventCreateWithFlags(&ev_fork, cudaEventDisableTiming);
        cudaEventCreateWithFlags(&ev_join, cudaEventDisableTiming);
        cudaFuncSetAttribute(hgemm<0,0>, cudaFuncAttributeMaxDynamicSharedMemorySize, SMEM_B);
        cudaFuncSetAttribute(hgemm<1,0>, cudaFuncAttributeMaxDynamicSharedMemorySize, SMEM_B);
        cudaFuncSetAttribute(hgemm<4,0>, cudaFuncAttributeMaxDynamicSharedMemorySize, SMEM_B);
        cudaFuncSetAttribute(hgemm<0,1>, cudaFuncAttributeMaxDynamicSharedMemorySize, SMEM_B);
        cudaFuncSetAttribute(hgemm<3,2>, cudaFuncAttributeMaxDynamicSharedMemorySize, SMEM_B);
        init_done = true;
    }

    WT5 wt;
    wt.src[0] = wq; wt.dst[0] = p_wqkt;
    wt.src[1] = wk; wt.dst[1] = p_wqkt + (size_t)1024 * D_;
    wt.src[2] = wv; wt.dst[2] = p_wvt;
    wt.src[3] = W1; wt.dst[3] = p_w1t;
    wt.src[4] = W2; wt.dst[4] = p_w2t;

    // fused LN1 + weight transpose
    prep_kernel<<<M_ + 5 * 1024, 256>>>(x, g1, be1, p_h, wt);

    // fork: vt on stream s1 concurrent with qk on default stream
    cudaEventRecord(ev_fork, 0);
    cudaStreamWaitEvent(s1, ev_fork, 0);

    // vt[b][d][t] = wvt[d][:] . h[b*T+t][:]  — 512 CTAs, one tile each, on s1
    hgemm<0,0><<<512, NT, SMEM_B, s1>>>(p_wvt, p_h, p_vt, nullptr, nullptr,
                                        D_, D_, D_, T_, 0, (size_t)T_*D_, (size_t)D_*T_,
                                        16, 8, 4);
    // qk = h @ [wq/32 | wk] — 1024 CTAs, one tile each, default stream
    hgemm<0,0><<<1024, NT, SMEM_B>>>(p_h, p_wqkt, p_qk, nullptr, nullptr,
                                     D_, D_, D_, 2048, 0, 0, 0, 16, 64, 1);

    // join: scores needs both qk and vt
    cudaEventRecord(ev_join, s1);
    cudaStreamWaitEvent(0, ev_join, 0);

    // scores (pre-scaled q): lower triangle only
    hgemm<0,1><<<GRID_P, NT, SMEM_B>>>(p_qk, p_qk + 1024, p_s, nullptr, nullptr,
                                       2048, 2048, D_, T_,
                                       (size_t)T_*2048, (size_t)T_*2048, (size_t)T_*T_,
                                       16, 16, 4);
    softmax_kernel<<<M_, 256>>>(p_s);
    // y = half(P @ V^T + x)  (cost-sorted schedule)
    hgemm<3,2><<<GRID_P, NT, SMEM_B>>>(p_s, p_vt, p_y, nullptr, x,
                                       T_, T_, T_, D_,
                                       (size_t)T_*T_, (size_t)D_*T_, (size_t)T_*D_,
                                       8, 16, 4);
    ln_half_kernel<<<M_, 256>>>(p_y, g2, be2, p_h2);
    hgemm<1,0><<<GRID_P, NT, SMEM_B>>>(p_h2, p_w1t, p_m1, b1, nullptr,
                                       D_, D_, D_, D_, 0, 0, 0, 8, 64, 1);
    // out = m1 @ W2 + b2 + y (half resid)
    hgemm<4,0><<<GRID_P, NT, SMEM_B>>>(p_m1, p_w2t, out, b2, p_y,
                                       D_, D_, D_, D_, 0, 0, 0, 8, 64, 1);
}